// round 3
// baseline (speedup 1.0000x reference)
#include <cuda_runtime.h>
#include <stdint.h>

// Problem dims (fixed for this problem instance)
#define N_NODES 20000
#define F_IN    8710
#define HID     1024
#define C_OUT   70
#define E_MAX   320000

// ---------------- scratch (static device globals; no cudaMalloc allowed) ----
__device__ float g_deg [N_NODES];
__device__ float g_dinv[N_NODES];
__device__ float g_h1  [(size_t)N_NODES * HID];   // x @ W1
__device__ float g_a1  [(size_t)N_NODES * HID];   // agg1 + b1, then relu+dropout in-place
__device__ float g_h2  [(size_t)N_NODES * C_OUT]; // h @ W2
__device__ float g_o2  [(size_t)N_NODES * C_OUT]; // agg2 + b2
__device__ int   g_edges[2 * E_MAX];              // normalized int32 [src | dst]
__device__ int   g_is64;

// TF32 round (RNA), matching XLA/cuBLAS default f32 matmul precision on GPU
__device__ __forceinline__ float tf32_rna(float x) {
    float r;
    asm("cvt.rna.tf32.f32 %0, %1;" : "=f"(r) : "f"(x));
    return r;
}

// ---------------- edge dtype detection + normalization ----------------------
__global__ void detect_edges_k(const void* edges) {
    const long long* p = (const long long*)edges;
    int valid = 0;
    for (int i = 0; i < 256; i++) {
        long long v = p[i];
        if (v >= 0 && v < N_NODES) valid++;
    }
    g_is64 = (valid >= 200) ? 1 : 0;
}

__global__ void conv_edges_k(const void* edges, int total) {
    int i = blockIdx.x * blockDim.x + threadIdx.x;
    if (i >= total) return;
    long long v = g_is64 ? ((const long long*)edges)[i]
                         : (long long)((const int*)edges)[i];
    g_edges[i] = (int)v;
}

// ---------------- degree / norm ---------------------------------------------
__global__ void deg_init_k(int n) {
    int i = blockIdx.x * blockDim.x + threadIdx.x;
    if (i < n) g_deg[i] = 1.0f;           // self loop
}
__global__ void deg_count_k(int E) {
    int e = blockIdx.x * blockDim.x + threadIdx.x;
    if (e < E) atomicAdd(&g_deg[g_edges[E + e]], 1.0f);  // deg over dst
}
__global__ void dinv_k(int n) {
    int i = blockIdx.x * blockDim.x + threadIdx.x;
    if (i < n) g_dinv[i] = rsqrtf(g_deg[i]);
}

// ---------------- SGEMM1: [M,K] x [K,N] -> g_h1, TF32-rounded inputs --------
__global__ __launch_bounds__(256) void sgemm1_k(
    const float* __restrict__ A, const float* __restrict__ B,
    int M, int N, int K)
{
    __shared__ float As[8][128];
    __shared__ float Bs[8][128];
    const int tid = threadIdx.x;
    const int ty = tid >> 4, tx = tid & 15;
    const int rowBase = blockIdx.y * 128;
    const int colBase = blockIdx.x * 128;

    const int aRow  = tid >> 1;          // 0..127
    const int aCol  = (tid & 1) << 2;    // 0 or 4
    const int bRow0 = tid >> 7;          // 0..1
    const int bCol  = tid & 127;

    float acc[8][8];
#pragma unroll
    for (int i = 0; i < 8; i++)
#pragma unroll
        for (int j = 0; j < 8; j++) acc[i][j] = 0.f;

    const int gr = rowBase + aRow;
    for (int k0 = 0; k0 < K; k0 += 8) {
#pragma unroll
        for (int j = 0; j < 4; j++) {
            int gk = k0 + aCol + j;
            float v = (gr < M && gk < K) ? A[(size_t)gr * K + gk] : 0.f;
            As[aCol + j][aRow] = tf32_rna(v);
        }
#pragma unroll
        for (int i = 0; i < 4; i++) {
            int r  = bRow0 + (i << 1);
            int gk = k0 + r;
            float v = (gk < K) ? B[(size_t)gk * N + colBase + bCol] : 0.f;
            Bs[r][bCol] = tf32_rna(v);
        }
        __syncthreads();
#pragma unroll
        for (int kk = 0; kk < 8; kk++) {
            float a[8], b[8];
#pragma unroll
            for (int i = 0; i < 8; i++) a[i] = As[kk][ty * 8 + i];
#pragma unroll
            for (int j = 0; j < 8; j++) b[j] = Bs[kk][tx * 8 + j];
#pragma unroll
            for (int i = 0; i < 8; i++)
#pragma unroll
                for (int j = 0; j < 8; j++) acc[i][j] += a[i] * b[j];
        }
        __syncthreads();
    }
#pragma unroll
    for (int i = 0; i < 8; i++) {
        int r = rowBase + ty * 8 + i;
        if (r < M) {
#pragma unroll
            for (int j = 0; j < 8; j++)
                g_h1[(size_t)r * N + colBase + tx * 8 + j] = acc[i][j];
        }
    }
}

// ---------------- agg1: self-loop + bias init, then edge scatter ------------
__global__ void agg1_init_k(const float* __restrict__ b1, int total) {
    int idx = blockIdx.x * blockDim.x + threadIdx.x;
    if (idx >= total) return;
    int n = idx >> 10, c = idx & 1023;
    float di = g_dinv[n];
    g_a1[idx] = b1[c] + g_h1[idx] * di * di;
}

__global__ void agg1_edges_k(int E) {
    int e = blockIdx.x;                 // one block per edge, 256 threads x float4
    int s = g_edges[e];
    int d = g_edges[E + e];
    float w = g_dinv[s] * g_dinv[d];
    const float4* hs = (const float4*)(g_h1 + (size_t)s * HID);
    float4 v = hs[threadIdx.x];
    float* ad = g_a1 + (size_t)d * HID + threadIdx.x * 4;
    atomicAdd(ad + 0, v.x * w);
    atomicAdd(ad + 1, v.y * w);
    atomicAdd(ad + 2, v.z * w);
    atomicAdd(ad + 3, v.w * w);
}

// ---------------- relu + JAX threefry dropout, PARTITIONABLE mode -----------
// bits(i) = x0 ^ x1 of threefry2x32(key=(0,42), counter=(hi(i)=0, lo(i)=i)).
// keep <=> uniform(bits) < 0.5 <=> MSB(bits) == 0. kept scaled by 2.
__device__ __forceinline__ uint2 threefry2x32(uint32_t c0, uint32_t c1) {
    const uint32_t ks0 = 0u, ks1 = 42u, ks2 = 0u ^ 42u ^ 0x1BD11BDAu;
    uint32_t x0 = c0 + ks0;
    uint32_t x1 = c1 + ks1;
#define TF_RND(r) { x0 += x1; x1 = (x1 << (r)) | (x1 >> (32 - (r))); x1 ^= x0; }
    TF_RND(13) TF_RND(15) TF_RND(26) TF_RND(6)   x0 += ks1; x1 += ks2 + 1u;
    TF_RND(17) TF_RND(29) TF_RND(16) TF_RND(24)  x0 += ks2; x1 += ks0 + 2u;
    TF_RND(13) TF_RND(15) TF_RND(26) TF_RND(6)   x0 += ks0; x1 += ks1 + 3u;
    TF_RND(17) TF_RND(29) TF_RND(16) TF_RND(24)  x0 += ks1; x1 += ks2 + 4u;
    TF_RND(13) TF_RND(15) TF_RND(26) TF_RND(6)   x0 += ks2; x1 += ks0 + 5u;
#undef TF_RND
    return make_uint2(x0, x1);
}

__global__ void relu_dropout_k(int total) {
    int i = blockIdx.x * blockDim.x + threadIdx.x;
    if (i >= total) return;
    uint2 r = threefry2x32(0u, (uint32_t)i);   // counter = (hi=0, lo=i)
    uint32_t bits = r.x ^ r.y;                 // 32-bit fold of the two output words
    float v = fmaxf(g_a1[i], 0.f);
    g_a1[i] = (bits & 0x80000000u) ? 0.f : 2.f * v;
}

// ---------------- GEMM2: [N,HID] x [HID,C_OUT] -> g_h2, TF32 inputs ---------
__global__ void gemm2_k(const float* __restrict__ W2, int total) {
    int idx = blockIdx.x * blockDim.x + threadIdx.x;
    if (idx >= total) return;
    int n = idx / C_OUT, c = idx - n * C_OUT;
    const float* hr = g_a1 + (size_t)n * HID;
    float acc = 0.f;
#pragma unroll 8
    for (int k = 0; k < HID; k++)
        acc += tf32_rna(hr[k]) * tf32_rna(W2[k * C_OUT + c]);
    g_h2[idx] = acc;
}

// ---------------- agg2 -------------------------------------------------------
__global__ void agg2_init_k(const float* __restrict__ b2, int total) {
    int idx = blockIdx.x * blockDim.x + threadIdx.x;
    if (idx >= total) return;
    int n = idx / C_OUT, c = idx - n * C_OUT;
    float di = g_dinv[n];
    g_o2[idx] = b2[c] + g_h2[idx] * di * di;
}

__global__ void agg2_edges_k(int E) {
    int warp = (blockIdx.x * blockDim.x + threadIdx.x) >> 5;
    int lane = threadIdx.x & 31;
    if (warp >= E) return;
    int s = g_edges[warp];
    int d = g_edges[E + warp];
    float w = g_dinv[s] * g_dinv[d];
    const float* hs = g_h2 + (size_t)s * C_OUT;
    float* od = g_o2 + (size_t)d * C_OUT;
    for (int c = lane; c < C_OUT; c += 32)
        atomicAdd(od + c, hs[c] * w);
}

// ---------------- log_softmax (warp per row) ---------------------------------
__global__ void logsoftmax_k(float* __restrict__ out, int n) {
    int row  = blockIdx.x * 8 + (threadIdx.x >> 5);
    int lane = threadIdx.x & 31;
    if (row >= n) return;
    const float* r = g_o2 + (size_t)row * C_OUT;
    float m = -1e30f;
    for (int c = lane; c < C_OUT; c += 32) m = fmaxf(m, r[c]);
#pragma unroll
    for (int o = 16; o; o >>= 1) m = fmaxf(m, __shfl_xor_sync(0xffffffffu, m, o));
    float s = 0.f;
    for (int c = lane; c < C_OUT; c += 32) s += expf(r[c] - m);
#pragma unroll
    for (int o = 16; o; o >>= 1) s += __shfl_xor_sync(0xffffffffu, s, o);
    float lse = m + logf(s);
    float* orow = out + (size_t)row * C_OUT;
    for (int c = lane; c < C_OUT; c += 32) orow[c] = r[c] - lse;
}

// ---------------- launch ------------------------------------------------------
extern "C" void kernel_launch(void* const* d_in, const int* in_sizes, int n_in,
                              void* d_out, int out_size) {
    const float* x     = (const float*)d_in[0];
    const void*  edges = d_in[1];
    const float* W1    = (const float*)d_in[2];
    const float* b1    = (const float*)d_in[3];
    const float* W2    = (const float*)d_in[4];
    const float* b2    = (const float*)d_in[5];
    float* out = (float*)d_out;

    const int E = in_sizes[1] / 2;
    const int N = N_NODES;

    detect_edges_k<<<1, 1>>>(edges);
    conv_edges_k<<<(2 * E + 255) / 256, 256>>>(edges, 2 * E);

    deg_init_k <<<(N + 255) / 256, 256>>>(N);
    deg_count_k<<<(E + 255) / 256, 256>>>(E);
    dinv_k     <<<(N + 255) / 256, 256>>>(N);

    dim3 g1(HID / 128, (N + 127) / 128);
    sgemm1_k<<<g1, 256>>>(x, W1, N, HID, F_IN);

    const int tot1 = N * HID;
    agg1_init_k <<<(tot1 + 255) / 256, 256>>>(b1, tot1);
    agg1_edges_k<<<E, 256>>>(E);

    relu_dropout_k<<<(tot1 + 255) / 256, 256>>>(tot1);

    const int tot2 = N * C_OUT;
    gemm2_k     <<<(tot2 + 255) / 256, 256>>>(W2, tot2);
    agg2_init_k <<<(tot2 + 255) / 256, 256>>>(b2, tot2);
    agg2_edges_k<<<(E + 7) / 8, 256>>>(E);

    logsoftmax_k<<<(N + 7) / 8, 256>>>(out, N);
}

// round 5
// speedup vs baseline: 4.0214x; 4.0214x over previous
#include <cuda_runtime.h>
#include <cuda_bf16.h>
#include <stdint.h>

// Problem dims (fixed)
#define N_NODES 20000
#define F_IN    8710
#define K_PAD   8768          // 274 * 32
#define HID     1024
#define C_OUT   70
#define E_MAX   320000

// GEMM1 tiling
#define BM 128
#define BN 128
#define BK 32
#define KTILES (K_PAD / BK)   // 274
#define APAD 40               // row stride in bf16 elems (80B, 16B-aligned, ldmatrix conflict-free)

// ---------------- scratch ----------------------------------------------------
__device__ float g_deg [N_NODES];
__device__ float g_dinv[N_NODES];
__device__ __nv_bfloat16 g_xb [(size_t)N_NODES * K_PAD];  // x in bf16, K-padded
__device__ __nv_bfloat16 g_w1t[(size_t)HID * K_PAD];      // W1^T in bf16, K-padded
__device__ float g_h1  [(size_t)N_NODES * HID];
__device__ float g_a1  [(size_t)N_NODES * HID];
__device__ float g_h2  [(size_t)N_NODES * C_OUT];
__device__ float g_o2  [(size_t)N_NODES * C_OUT];
__device__ int   g_edges[2 * E_MAX];
__device__ int   g_is64;

// TF32 round (RNA) for GEMM2 (matches XLA default f32 matmul)
__device__ __forceinline__ float tf32_rna(float x) {
    float r; asm("cvt.rna.tf32.f32 %0, %1;" : "=f"(r) : "f"(x)); return r;
}

__device__ __forceinline__ uint32_t smem_u32(const void* p) {
    uint32_t a;
    asm("{ .reg .u64 t; cvta.to.shared.u64 t, %1; cvt.u32.u64 %0, t; }" : "=r"(a) : "l"(p));
    return a;
}

// ---------------- edge dtype detection + normalization ----------------------
__global__ void detect_edges_k(const void* edges) {
    const long long* p = (const long long*)edges;
    int valid = 0;
    for (int i = 0; i < 256; i++) {
        long long v = p[i];
        if (v >= 0 && v < N_NODES) valid++;
    }
    g_is64 = (valid >= 200) ? 1 : 0;
}
__global__ void conv_edges_k(const void* edges, int total) {
    int i = blockIdx.x * blockDim.x + threadIdx.x;
    if (i >= total) return;
    long long v = g_is64 ? ((const long long*)edges)[i]
                         : (long long)((const int*)edges)[i];
    g_edges[i] = (int)v;
}

// ---------------- degree / norm ---------------------------------------------
__global__ void deg_init_k(int n) {
    int i = blockIdx.x * blockDim.x + threadIdx.x;
    if (i < n) g_deg[i] = 1.0f;
}
__global__ void deg_count_k(int E) {
    int e = blockIdx.x * blockDim.x + threadIdx.x;
    if (e < E) atomicAdd(&g_deg[g_edges[E + e]], 1.0f);
}
__global__ void dinv_k(int n) {
    int i = blockIdx.x * blockDim.x + threadIdx.x;
    if (i < n) g_dinv[i] = rsqrtf(g_deg[i]);
}

// ---------------- conversions -------------------------------------------------
__global__ void conv_x_k(const float* __restrict__ x) {
    int k = blockIdx.x * 256 + threadIdx.x;
    int r = blockIdx.y;
    if (k >= K_PAD) return;
    float v = (k < F_IN) ? x[(size_t)r * F_IN + k] : 0.f;
    g_xb[(size_t)r * K_PAD + k] = __float2bfloat16(v);
}
__global__ void conv_w1t_k(const float* __restrict__ W1) {
    __shared__ __nv_bfloat16 t[32][33];
    int k0 = blockIdx.x * 32, n0 = blockIdx.y * 32;
    int tx = threadIdx.x, ty = threadIdx.y;
#pragma unroll
    for (int i = 0; i < 32; i += 8) {
        int k = k0 + ty + i, n = n0 + tx;
        float v = (k < F_IN) ? W1[(size_t)k * HID + n] : 0.f;
        t[ty + i][tx] = __float2bfloat16(v);
    }
    __syncthreads();
#pragma unroll
    for (int i = 0; i < 32; i += 8) {
        int n = n0 + ty + i, k = k0 + tx;
        g_w1t[(size_t)n * K_PAD + k] = t[tx][ty + i];
    }
}

// ---------------- GEMM1: bf16 HMMA (mma.sync m16n8k16), cp.async pipeline ----
__device__ __forceinline__ void ldsm_x4(uint32_t* r, uint32_t addr) {
    asm volatile("ldmatrix.sync.aligned.m8n8.x4.shared.b16 {%0,%1,%2,%3}, [%4];"
        : "=r"(r[0]), "=r"(r[1]), "=r"(r[2]), "=r"(r[3]) : "r"(addr));
}
__device__ __forceinline__ void ldsm_x2(uint32_t* r, uint32_t addr) {
    asm volatile("ldmatrix.sync.aligned.m8n8.x2.shared.b16 {%0,%1}, [%2];"
        : "=r"(r[0]), "=r"(r[1]) : "r"(addr));
}
__device__ __forceinline__ void mma16816(float* d, const uint32_t* a, const uint32_t* b) {
    asm volatile(
        "mma.sync.aligned.m16n8k16.row.col.f32.bf16.bf16.f32 "
        "{%0,%1,%2,%3}, {%4,%5,%6,%7}, {%8,%9}, {%0,%1,%2,%3};"
        : "+f"(d[0]), "+f"(d[1]), "+f"(d[2]), "+f"(d[3])
        : "r"(a[0]), "r"(a[1]), "r"(a[2]), "r"(a[3]), "r"(b[0]), "r"(b[1]));
}
#define CP_ASYNC16(dst, src) \
    asm volatile("cp.async.cg.shared.global [%0], [%1], 16;" :: "r"(dst), "l"(src))
#define CP_COMMIT() asm volatile("cp.async.commit_group;" ::: "memory")
#define CP_WAIT0()  asm volatile("cp.async.wait_group 0;" ::: "memory")

__global__ __launch_bounds__(256) void gemm1_tc_k() {
    // 2 stages x (A: 128x40 bf16 = 10240B, B: 128x40 bf16 = 10240B)
    __shared__ __align__(16) __nv_bfloat16 As[2][BM * APAD];
    __shared__ __align__(16) __nv_bfloat16 Bs[2][BN * APAD];

    const int tid  = threadIdx.x;
    const int wid  = tid >> 5, lane = tid & 31;
    const int mBase = blockIdx.y * BM;
    const int nBase = blockIdx.x * BN;
    const int mo = (wid >> 2) * 64;    // warp m offset (0,64)
    const int no = (wid & 3) * 32;     // warp n offset (0,32,64,96)

    // prefetch coordinates: 512 chunks of 16B per tile; thread handles idx=tid, tid+256
    const int r0 = tid >> 2, c0 = (tid & 3) * 8;           // chunk 0: row, col(bf16)
    const int r1 = (tid + 256) >> 2, c1 = c0;              // chunk 1
    const int amr0 = (mBase + r0 < N_NODES) ? mBase + r0 : N_NODES - 1;
    const int amr1 = (mBase + r1 < N_NODES) ? mBase + r1 : N_NODES - 1;
    const __nv_bfloat16* aSrc0 = g_xb + (size_t)amr0 * K_PAD + c0;
    const __nv_bfloat16* aSrc1 = g_xb + (size_t)amr1 * K_PAD + c1;
    const __nv_bfloat16* bSrc0 = g_w1t + (size_t)(nBase + r0) * K_PAD + c0;
    const __nv_bfloat16* bSrc1 = g_w1t + (size_t)(nBase + r1) * K_PAD + c1;

    uint32_t aDst0[2], aDst1[2], bDst0[2], bDst1[2];
#pragma unroll
    for (int s = 0; s < 2; s++) {
        aDst0[s] = smem_u32(&As[s][r0 * APAD + c0]);
        aDst1[s] = smem_u32(&As[s][r1 * APAD + c1]);
        bDst0[s] = smem_u32(&Bs[s][r0 * APAD + c0]);
        bDst1[s] = smem_u32(&Bs[s][r1 * APAD + c1]);
    }

    // ldmatrix per-lane base offsets (elements)
    const int lg = lane >> 3, lr = lane & 7;
    // A x4: group g: row += (g&1)*8, col += (g>>1)*8
    const uint32_t aLdBase[2] = {
        smem_u32(&As[0][(mo + (lg & 1) * 8 + lr) * APAD + (lg >> 1) * 8]),
        smem_u32(&As[1][(mo + (lg & 1) * 8 + lr) * APAD + (lg >> 1) * 8]) };
    // B x2: lanes 0-15: group g: col += g*8 (lanes 16-31 mirror 0-15, ignored)
    const int bl = lane & 15, bg = bl >> 3, br = bl & 7;
    const uint32_t bLdBase[2] = {
        smem_u32(&Bs[0][(no + br) * APAD + bg * 8]),
        smem_u32(&Bs[1][(no + br) * APAD + bg * 8]) };

    float acc[4][4][4];
#pragma unroll
    for (int i = 0; i < 4; i++)
#pragma unroll
        for (int j = 0; j < 4; j++)
#pragma unroll
            for (int q = 0; q < 4; q++) acc[i][j][q] = 0.f;

    // prefetch tile 0 into stage 0
    {
        CP_ASYNC16(aDst0[0], aSrc0);
        CP_ASYNC16(aDst1[0], aSrc1);
        CP_ASYNC16(bDst0[0], bSrc0);
        CP_ASYNC16(bDst1[0], bSrc1);
        CP_COMMIT();
    }

    for (int it = 0; it < KTILES; it++) {
        const int s = it & 1;
        CP_WAIT0();
        __syncthreads();
        if (it + 1 < KTILES) {
            const int ns = s ^ 1;
            const size_t ko = (size_t)(it + 1) * BK;
            CP_ASYNC16(aDst0[ns], aSrc0 + ko);
            CP_ASYNC16(aDst1[ns], aSrc1 + ko);
            CP_ASYNC16(bDst0[ns], bSrc0 + ko);
            CP_ASYNC16(bDst1[ns], bSrc1 + ko);
            CP_COMMIT();
        }
#pragma unroll
        for (int ks = 0; ks < 2; ks++) {
            uint32_t a[4][4], b[4][2];
#pragma unroll
            for (int mi = 0; mi < 4; mi++)
                ldsm_x4(a[mi], aLdBase[s] + (mi * 16 * APAD + ks * 16) * 2);
#pragma unroll
            for (int nj = 0; nj < 4; nj++)
                ldsm_x2(b[nj], bLdBase[s] + (nj * 8 * APAD + ks * 16) * 2);
#pragma unroll
            for (int mi = 0; mi < 4; mi++)
#pragma unroll
                for (int nj = 0; nj < 4; nj++)
                    mma16816(acc[mi][nj], a[mi], b[nj]);
        }
        __syncthreads();
    }

    // epilogue: direct fp32 stores
    const int erow = lane >> 2, ecol = (lane & 3) * 2;
#pragma unroll
    for (int mi = 0; mi < 4; mi++) {
        const int gr0 = mBase + mo + mi * 16 + erow;
        const int gr1 = gr0 + 8;
#pragma unroll
        for (int nj = 0; nj < 4; nj++) {
            const int gc = nBase + no + nj * 8 + ecol;
            if (gr0 < N_NODES)
                *(float2*)(g_h1 + (size_t)gr0 * HID + gc) = make_float2(acc[mi][nj][0], acc[mi][nj][1]);
            if (gr1 < N_NODES)
                *(float2*)(g_h1 + (size_t)gr1 * HID + gc) = make_float2(acc[mi][nj][2], acc[mi][nj][3]);
        }
    }
}

// ---------------- agg1 --------------------------------------------------------
__global__ void agg1_init_k(const float* __restrict__ b1, int total) {
    int idx = blockIdx.x * blockDim.x + threadIdx.x;
    if (idx >= total) return;
    int n = idx >> 10, c = idx & 1023;
    float di = g_dinv[n];
    g_a1[idx] = b1[c] + g_h1[idx] * di * di;
}
__global__ void agg1_edges_k(int E) {
    int e = blockIdx.x;
    int s = g_edges[e];
    int d = g_edges[E + e];
    float w = g_dinv[s] * g_dinv[d];
    const float4* hs = (const float4*)(g_h1 + (size_t)s * HID);
    float4 v = hs[threadIdx.x];
    float* ad = g_a1 + (size_t)d * HID + threadIdx.x * 4;
    atomicAdd(ad + 0, v.x * w);
    atomicAdd(ad + 1, v.y * w);
    atomicAdd(ad + 2, v.z * w);
    atomicAdd(ad + 3, v.w * w);
}

// ---------------- relu + JAX threefry dropout (partitionable, key 42) --------
__device__ __forceinline__ uint2 threefry2x32(uint32_t c0, uint32_t c1) {
    const uint32_t ks0 = 0u, ks1 = 42u, ks2 = 0u ^ 42u ^ 0x1BD11BDAu;
    uint32_t x0 = c0 + ks0;
    uint32_t x1 = c1 + ks1;
#define TF_RND(r) { x0 += x1; x1 = (x1 << (r)) | (x1 >> (32 - (r))); x1 ^= x0; }
    TF_RND(13) TF_RND(15) TF_RND(26) TF_RND(6)   x0 += ks1; x1 += ks2 + 1u;
    TF_RND(17) TF_RND(29) TF_RND(16) TF_RND(24)  x0 += ks2; x1 += ks0 + 2u;
    TF_RND(13) TF_RND(15) TF_RND(26) TF_RND(6)   x0 += ks0; x1 += ks1 + 3u;
    TF_RND(17) TF_RND(29) TF_RND(16) TF_RND(24)  x0 += ks1; x1 += ks2 + 4u;
    TF_RND(13) TF_RND(15) TF_RND(26) TF_RND(6)   x0 += ks2; x1 += ks0 + 5u;
#undef TF_RND
    return make_uint2(x0, x1);
}
__global__ void relu_dropout_k(int total) {
    int i = blockIdx.x * blockDim.x + threadIdx.x;
    if (i >= total) return;
    uint2 r = threefry2x32(0u, (uint32_t)i);
    uint32_t bits = r.x ^ r.y;
    float v = fmaxf(g_a1[i], 0.f);
    g_a1[i] = (bits & 0x80000000u) ? 0.f : 2.f * v;
}

// ---------------- GEMM2 (TF32-rounded FMA) ------------------------------------
__global__ void gemm2_k(const float* __restrict__ W2, int total) {
    int idx = blockIdx.x * blockDim.x + threadIdx.x;
    if (idx >= total) return;
    int n = idx / C_OUT, c = idx - n * C_OUT;
    const float* hr = g_a1 + (size_t)n * HID;
    float acc = 0.f;
#pragma unroll 8
    for (int k = 0; k < HID; k++)
        acc += tf32_rna(hr[k]) * tf32_rna(W2[k * C_OUT + c]);
    g_h2[idx] = acc;
}

// ---------------- agg2 ---------------------------------------------------------
__global__ void agg2_init_k(const float* __restrict__ b2, int total) {
    int idx = blockIdx.x * blockDim.x + threadIdx.x;
    if (idx >= total) return;
    int n = idx / C_OUT, c = idx - n * C_OUT;
    float di = g_dinv[n];
    g_o2[idx] = b2[c] + g_h2[idx] * di * di;
}
__global__ void agg2_edges_k(int E) {
    int warp = (blockIdx.x * blockDim.x + threadIdx.x) >> 5;
    int lane = threadIdx.x & 31;
    if (warp >= E) return;
    int s = g_edges[warp];
    int d = g_edges[E + warp];
    float w = g_dinv[s] * g_dinv[d];
    const float* hs = g_h2 + (size_t)s * C_OUT;
    float* od = g_o2 + (size_t)d * C_OUT;
    for (int c = lane; c < C_OUT; c += 32)
        atomicAdd(od + c, hs[c] * w);
}

// ---------------- log_softmax ---------------------------------------------------
__global__ void logsoftmax_k(float* __restrict__ out, int n) {
    int row  = blockIdx.x * 8 + (threadIdx.x >> 5);
    int lane = threadIdx.x & 31;
    if (row >= n) return;
    const float* r = g_o2 + (size_t)row * C_OUT;
    float m = -1e30f;
    for (int c = lane; c < C_OUT; c += 32) m = fmaxf(m, r[c]);
#pragma unroll
    for (int o = 16; o; o >>= 1) m = fmaxf(m, __shfl_xor_sync(0xffffffffu, m, o));
    float s = 0.f;
    for (int c = lane; c < C_OUT; c += 32) s += expf(r[c] - m);
#pragma unroll
    for (int o = 16; o; o >>= 1) s += __shfl_xor_sync(0xffffffffu, s, o);
    float lse = m + logf(s);
    float* orow = out + (size_t)row * C_OUT;
    for (int c = lane; c < C_OUT; c += 32) orow[c] = r[c] - lse;
}

// ---------------- launch ---------------------------------------------------------
extern "C" void kernel_launch(void* const* d_in, const int* in_sizes, int n_in,
                              void* d_out, int out_size) {
    const float* x     = (const float*)d_in[0];
    const void*  edges = d_in[1];
    const float* W1    = (const float*)d_in[2];
    const float* b1    = (const float*)d_in[3];
    const float* W2    = (const float*)d_in[4];
    const float* b2    = (const float*)d_in[5];
    float* out = (float*)d_out;

    const int E = in_sizes[1] / 2;
    const int N = N_NODES;

    detect_edges_k<<<1, 1>>>(edges);
    conv_edges_k<<<(2 * E + 255) / 256, 256>>>(edges, 2 * E);

    deg_init_k <<<(N + 255) / 256, 256>>>(N);
    deg_count_k<<<(E + 255) / 256, 256>>>(E);
    dinv_k     <<<(N + 255) / 256, 256>>>(N);

    // bf16 conversions (padded K)
    conv_x_k  <<<dim3((K_PAD + 255) / 256, N), 256>>>(x);
    conv_w1t_k<<<dim3(K_PAD / 32, HID / 32), dim3(32, 8)>>>(W1);

    // GEMM1 on HMMA tensor cores: grid (N-tiles=8, M-tiles=157)
    gemm1_tc_k<<<dim3(HID / BN, (N + BM - 1) / BM), 256>>>();

    const int tot1 = N * HID;
    agg1_init_k <<<(tot1 + 255) / 256, 256>>>(b1, tot1);
    agg1_edges_k<<<E, 256>>>(E);

    relu_dropout_k<<<(tot1 + 255) / 256, 256>>>(tot1);

    const int tot2 = N * C_OUT;
    gemm2_k     <<<(tot2 + 255) / 256, 256>>>(W2, tot2);
    agg2_init_k <<<(tot2 + 255) / 256, 256>>>(b2, tot2);
    agg2_edges_k<<<(E + 7) / 8, 256>>>(E);

    logsoftmax_k<<<(N + 7) / 8, 256>>>(out, N);
}

// round 7
// speedup vs baseline: 5.2016x; 1.2935x over previous
#include <cuda_runtime.h>
#include <cuda_bf16.h>
#include <stdint.h>

// Problem dims (fixed)
#define N_NODES 20000
#define F_IN    8710
#define K_PAD   8768          // 274 * 32
#define HID     1024
#define C_OUT   70
#define E_MAX   320000

// GEMM1 tiling
#define BM 128
#define BN 128
#define BK 32
#define KTILES (K_PAD / BK)   // 274
#define APAD 40               // smem row stride (80B, 16B aligned, conflict-free)

// ---------------- scratch ----------------------------------------------------
__device__ float g_dinv[N_NODES];
__device__ int   g_cnt [N_NODES];
__device__ int   g_cur [N_NODES];
__device__ int   g_rowptr[N_NODES + 1];
__device__ int   g_csrc[E_MAX];
__device__ __nv_bfloat16 g_xb [(size_t)N_NODES * K_PAD];  // x bf16, K-padded
__device__ __nv_bfloat16 g_w1t[(size_t)HID * K_PAD];      // W1^T bf16
__device__ float g_h1  [(size_t)N_NODES * HID];
__device__ float g_a1  [(size_t)N_NODES * HID];           // post agg+relu+dropout, fp32
__device__ float g_h2  [(size_t)N_NODES * C_OUT];
__device__ float g_o2  [(size_t)N_NODES * C_OUT];
__device__ int   g_edges[2 * E_MAX];
__device__ int   g_is64;

// TF32 round (RNA) for GEMM2 (matches XLA default f32 matmul)
__device__ __forceinline__ float tf32_rna(float x) {
    float r; asm("cvt.rna.tf32.f32 %0, %1;" : "=f"(r) : "f"(x)); return r;
}

__device__ __forceinline__ uint32_t smem_u32(const void* p) {
    uint32_t a;
    asm("{ .reg .u64 t; cvta.to.shared.u64 t, %1; cvt.u32.u64 %0, t; }" : "=r"(a) : "l"(p));
    return a;
}

// ---------------- edge dtype detection + normalization ----------------------
__global__ void detect_edges_k(const void* edges) {
    const long long* p = (const long long*)edges;
    int valid = 0;
    for (int i = 0; i < 256; i++) {
        long long v = p[i];
        if (v >= 0 && v < N_NODES) valid++;
    }
    g_is64 = (valid >= 200) ? 1 : 0;
}
__global__ void conv_edges_k(const void* edges, int total) {
    int i = blockIdx.x * blockDim.x + threadIdx.x;
    if (i >= total) return;
    long long v = g_is64 ? ((const long long*)edges)[i]
                         : (long long)((const int*)edges)[i];
    g_edges[i] = (int)v;
}

// ---------------- CSR build ---------------------------------------------------
__global__ void init0_k(int n) {
    int i = blockIdx.x * blockDim.x + threadIdx.x;
    if (i < n) { g_cnt[i] = 0; g_cur[i] = 0; }
}
__global__ void cnt_k(int E) {
    int e = blockIdx.x * blockDim.x + threadIdx.x;
    if (e < E) atomicAdd(&g_cnt[g_edges[E + e]], 1);
}
__global__ void scan_dinv_k() {
    __shared__ int part[512];
    const int t = threadIdx.x;
    const int CH = (N_NODES + 511) / 512;   // 40
    const int base = t * CH;
    int sum = 0;
    for (int j = 0; j < CH; j++) {
        int n = base + j;
        if (n < N_NODES) sum += g_cnt[n];
    }
    part[t] = sum;
    __syncthreads();
    for (int off = 1; off < 512; off <<= 1) {
        int v = (t >= off) ? part[t - off] : 0;
        __syncthreads();
        part[t] += v;
        __syncthreads();
    }
    int run = (t > 0) ? part[t - 1] : 0;
    for (int j = 0; j < CH; j++) {
        int n = base + j;
        if (n < N_NODES) {
            g_rowptr[n] = run;
            int c = g_cnt[n];
            run += c;
            g_dinv[n] = rsqrtf((float)(c + 1));
        }
    }
    if (t == 511) g_rowptr[N_NODES] = run;
}
__global__ void scatter_k(int E) {
    int e = blockIdx.x * blockDim.x + threadIdx.x;
    if (e >= E) return;
    int s = g_edges[e];
    int d = g_edges[E + e];
    int pos = g_rowptr[d] + atomicAdd(&g_cur[d], 1);
    g_csrc[pos] = s;
}

// ---------------- conversions -------------------------------------------------
__global__ void conv_x_k(const float* __restrict__ x) {
    int k = blockIdx.x * 256 + threadIdx.x;
    int r = blockIdx.y;
    if (k >= K_PAD) return;
    float v = (k < F_IN) ? x[(size_t)r * F_IN + k] : 0.f;
    g_xb[(size_t)r * K_PAD + k] = __float2bfloat16(v);
}
__global__ void conv_w1t_k(const float* __restrict__ W1) {
    __shared__ __nv_bfloat16 t[32][33];
    int k0 = blockIdx.x * 32, n0 = blockIdx.y * 32;
    int tx = threadIdx.x, ty = threadIdx.y;
#pragma unroll
    for (int i = 0; i < 32; i += 8) {
        int k = k0 + ty + i, n = n0 + tx;
        float v = (k < F_IN) ? W1[(size_t)k * HID + n] : 0.f;
        t[ty + i][tx] = __float2bfloat16(v);
    }
    __syncthreads();
#pragma unroll
    for (int i = 0; i < 32; i += 8) {
        int n = n0 + ty + i, k = k0 + tx;
        g_w1t[(size_t)n * K_PAD + k] = t[tx][ty + i];
    }
}

// ---------------- GEMM1: bf16 HMMA (mma.sync m16n8k16), cp.async 2-stage -----
__device__ __forceinline__ void ldsm_x4(uint32_t* r, uint32_t addr) {
    asm volatile("ldmatrix.sync.aligned.m8n8.x4.shared.b16 {%0,%1,%2,%3}, [%4];"
        : "=r"(r[0]), "=r"(r[1]), "=r"(r[2]), "=r"(r[3]) : "r"(addr));
}
__device__ __forceinline__ void ldsm_x2(uint32_t* r, uint32_t addr) {
    asm volatile("ldmatrix.sync.aligned.m8n8.x2.shared.b16 {%0,%1}, [%2];"
        : "=r"(r[0]), "=r"(r[1]) : "r"(addr));
}
__device__ __forceinline__ void mma16816(float* d, const uint32_t* a, const uint32_t* b) {
    asm volatile(
        "mma.sync.aligned.m16n8k16.row.col.f32.bf16.bf16.f32 "
        "{%0,%1,%2,%3}, {%4,%5,%6,%7}, {%8,%9}, {%0,%1,%2,%3};"
        : "+f"(d[0]), "+f"(d[1]), "+f"(d[2]), "+f"(d[3])
        : "r"(a[0]), "r"(a[1]), "r"(a[2]), "r"(a[3]), "r"(b[0]), "r"(b[1]));
}
#define CP_ASYNC16(dst, src) \
    asm volatile("cp.async.cg.shared.global [%0], [%1], 16;" :: "r"(dst), "l"(src))
#define CP_COMMIT() asm volatile("cp.async.commit_group;" ::: "memory")
#define CP_WAIT0()  asm volatile("cp.async.wait_group 0;" ::: "memory")

__global__ __launch_bounds__(256) void gemm1_tc_k() {
    __shared__ __align__(16) __nv_bfloat16 As[2][BM * APAD];
    __shared__ __align__(16) __nv_bfloat16 Bs[2][BN * APAD];

    const int tid  = threadIdx.x;
    const int wid  = tid >> 5, lane = tid & 31;
    const int mBase = blockIdx.y * BM;
    const int nBase = blockIdx.x * BN;
    const int mo = (wid >> 2) * 64;
    const int no = (wid & 3) * 32;

    const int r0 = tid >> 2, c0 = (tid & 3) * 8;
    const int r1 = (tid + 256) >> 2, c1 = c0;
    const int amr0 = (mBase + r0 < N_NODES) ? mBase + r0 : N_NODES - 1;
    const int amr1 = (mBase + r1 < N_NODES) ? mBase + r1 : N_NODES - 1;
    const __nv_bfloat16* aSrc0 = g_xb + (size_t)amr0 * K_PAD + c0;
    const __nv_bfloat16* aSrc1 = g_xb + (size_t)amr1 * K_PAD + c1;
    const __nv_bfloat16* bSrc0 = g_w1t + (size_t)(nBase + r0) * K_PAD + c0;
    const __nv_bfloat16* bSrc1 = g_w1t + (size_t)(nBase + r1) * K_PAD + c1;

    uint32_t aDst0[2], aDst1[2], bDst0[2], bDst1[2];
#pragma unroll
    for (int s = 0; s < 2; s++) {
        aDst0[s] = smem_u32(&As[s][r0 * APAD + c0]);
        aDst1[s] = smem_u32(&As[s][r1 * APAD + c1]);
        bDst0[s] = smem_u32(&Bs[s][r0 * APAD + c0]);
        bDst1[s] = smem_u32(&Bs[s][r1 * APAD + c1]);
    }

    const int lg = lane >> 3, lr = lane & 7;
    const uint32_t aLdBase[2] = {
        smem_u32(&As[0][(mo + (lg & 1) * 8 + lr) * APAD + (lg >> 1) * 8]),
        smem_u32(&As[1][(mo + (lg & 1) * 8 + lr) * APAD + (lg >> 1) * 8]) };
    const int bl = lane & 15, bg = bl >> 3, br = bl & 7;
    const uint32_t bLdBase[2] = {
        smem_u32(&Bs[0][(no + br) * APAD + bg * 8]),
        smem_u32(&Bs[1][(no + br) * APAD + bg * 8]) };

    float acc[4][4][4];
#pragma unroll
    for (int i = 0; i < 4; i++)
#pragma unroll
        for (int j = 0; j < 4; j++)
#pragma unroll
            for (int q = 0; q < 4; q++) acc[i][j][q] = 0.f;

    CP_ASYNC16(aDst0[0], aSrc0);
    CP_ASYNC16(aDst1[0], aSrc1);
    CP_ASYNC16(bDst0[0], bSrc0);
    CP_ASYNC16(bDst1[0], bSrc1);
    CP_COMMIT();

    for (int it = 0; it < KTILES; it++) {
        const int s = it & 1;
        CP_WAIT0();
        __syncthreads();
        if (it + 1 < KTILES) {
            const int ns = s ^ 1;
            const size_t ko = (size_t)(it + 1) * BK;
            CP_ASYNC16(aDst0[ns], aSrc0 + ko);
            CP_ASYNC16(aDst1[ns], aSrc1 + ko);
            CP_ASYNC16(bDst0[ns], bSrc0 + ko);
            CP_ASYNC16(bDst1[ns], bSrc1 + ko);
            CP_COMMIT();
        }
#pragma unroll
        for (int ks = 0; ks < 2; ks++) {
            uint32_t a[4][4], b[4][2];
#pragma unroll
            for (int mi = 0; mi < 4; mi++)
                ldsm_x4(a[mi], aLdBase[s] + (mi * 16 * APAD + ks * 16) * 2);
#pragma unroll
            for (int nj = 0; nj < 4; nj++)
                ldsm_x2(b[nj], bLdBase[s] + (nj * 8 * APAD + ks * 16) * 2);
#pragma unroll
            for (int mi = 0; mi < 4; mi++)
#pragma unroll
                for (int nj = 0; nj < 4; nj++)
                    mma16816(acc[mi][nj], a[mi], b[nj]);
        }
        __syncthreads();
    }

    const int erow = lane >> 2, ecol = (lane & 3) * 2;
#pragma unroll
    for (int mi = 0; mi < 4; mi++) {
        const int gr0 = mBase + mo + mi * 16 + erow;
        const int gr1 = gr0 + 8;
#pragma unroll
        for (int nj = 0; nj < 4; nj++) {
            const int gc = nBase + no + nj * 8 + ecol;
            if (gr0 < N_NODES)
                *(float2*)(g_h1 + (size_t)gr0 * HID + gc) = make_float2(acc[mi][nj][0], acc[mi][nj][1]);
            if (gr1 < N_NODES)
                *(float2*)(g_h1 + (size_t)gr1 * HID + gc) = make_float2(acc[mi][nj][2], acc[mi][nj][3]);
        }
    }
}

// ---------------- threefry (JAX partitionable, key=(0,42)) --------------------
__device__ __forceinline__ uint32_t tf_bits(uint32_t i) {
    const uint32_t ks0 = 0u, ks1 = 42u, ks2 = 0u ^ 42u ^ 0x1BD11BDAu;
    uint32_t x0 = 0u + ks0;
    uint32_t x1 = i + ks1;
#define TF_RND(r) { x0 += x1; x1 = (x1 << (r)) | (x1 >> (32 - (r))); x1 ^= x0; }
    TF_RND(13) TF_RND(15) TF_RND(26) TF_RND(6)   x0 += ks1; x1 += ks2 + 1u;
    TF_RND(17) TF_RND(29) TF_RND(16) TF_RND(24)  x0 += ks2; x1 += ks0 + 2u;
    TF_RND(13) TF_RND(15) TF_RND(26) TF_RND(6)   x0 += ks0; x1 += ks1 + 3u;
    TF_RND(17) TF_RND(29) TF_RND(16) TF_RND(24)  x0 += ks1; x1 += ks2 + 4u;
    TF_RND(13) TF_RND(15) TF_RND(26) TF_RND(6)   x0 += ks2; x1 += ks0 + 5u;
#undef TF_RND
    return x0 ^ x1;
}

// ---------------- fused agg1 + bias + relu + dropout (fp32 out) ---------------
// one block per dst node, 256 threads x float4 (1024 cols)
__global__ __launch_bounds__(256) void spmm1_k(const float* __restrict__ b1) {
    __shared__ int sidx[512];
    const int d = blockIdx.x;
    const int tid = threadIdx.x;
    const float di = g_dinv[d];
    const int beg = g_rowptr[d], end = g_rowptr[d + 1];

    float4 acc = *(const float4*)(g_h1 + (size_t)d * HID + tid * 4);
    const float dii = di * di;
    acc.x *= dii; acc.y *= dii; acc.z *= dii; acc.w *= dii;
    float4 bv = *(const float4*)(b1 + tid * 4);
    acc.x += bv.x; acc.y += bv.y; acc.z += bv.z; acc.w += bv.w;

    for (int chunk = beg; chunk < end; chunk += 512) {
        int n = min(512, end - chunk);
        __syncthreads();
        if (tid < n)       sidx[tid]       = g_csrc[chunk + tid];
        if (tid + 256 < n) sidx[tid + 256] = g_csrc[chunk + tid + 256];
        __syncthreads();
        for (int i = 0; i < n; i++) {
            int s = sidx[i];
            float w = g_dinv[s] * di;
            float4 v = *(const float4*)(g_h1 + (size_t)s * HID + tid * 4);
            acc.x += v.x * w; acc.y += v.y * w; acc.z += v.z * w; acc.w += v.w * w;
        }
    }

    const uint32_t idx = (uint32_t)d * HID + tid * 4;
    float v0 = fmaxf(acc.x, 0.f), v1 = fmaxf(acc.y, 0.f);
    float v2 = fmaxf(acc.z, 0.f), v3 = fmaxf(acc.w, 0.f);
    v0 = (tf_bits(idx + 0) & 0x80000000u) ? 0.f : 2.f * v0;
    v1 = (tf_bits(idx + 1) & 0x80000000u) ? 0.f : 2.f * v1;
    v2 = (tf_bits(idx + 2) & 0x80000000u) ? 0.f : 2.f * v2;
    v3 = (tf_bits(idx + 3) & 0x80000000u) ? 0.f : 2.f * v3;
    *(float4*)(g_a1 + (size_t)d * HID + tid * 4) = make_float4(v0, v1, v2, v3);
}

// ---------------- GEMM2 (TF32-rounded FMA, proven R5 code) --------------------
__global__ void gemm2_k(const float* __restrict__ W2, int total) {
    int idx = blockIdx.x * blockDim.x + threadIdx.x;
    if (idx >= total) return;
    int n = idx / C_OUT, c = idx - n * C_OUT;
    const float* hr = g_a1 + (size_t)n * HID;
    float acc = 0.f;
#pragma unroll 8
    for (int k = 0; k < HID; k++)
        acc += tf32_rna(hr[k]) * tf32_rna(W2[k * C_OUT + c]);
    g_h2[idx] = acc;
}

// ---------------- agg2 (proven R5 atomic path) ---------------------------------
__global__ void agg2_init_k(const float* __restrict__ b2, int total) {
    int idx = blockIdx.x * blockDim.x + threadIdx.x;
    if (idx >= total) return;
    int n = idx / C_OUT, c = idx - n * C_OUT;
    float di = g_dinv[n];
    g_o2[idx] = b2[c] + g_h2[idx] * di * di;
}
__global__ void agg2_edges_k(int E) {
    int warp = (blockIdx.x * blockDim.x + threadIdx.x) >> 5;
    int lane = threadIdx.x & 31;
    if (warp >= E) return;
    int s = g_edges[warp];
    int d = g_edges[E + warp];
    float w = g_dinv[s] * g_dinv[d];
    const float* hs = g_h2 + (size_t)s * C_OUT;
    float* od = g_o2 + (size_t)d * C_OUT;
    for (int c = lane; c < C_OUT; c += 32)
        atomicAdd(od + c, hs[c] * w);
}

// ---------------- log_softmax (proven R5) ---------------------------------------
__global__ void logsoftmax_k(float* __restrict__ out, int n) {
    int row  = blockIdx.x * 8 + (threadIdx.x >> 5);
    int lane = threadIdx.x & 31;
    if (row >= n) return;
    const float* r = g_o2 + (size_t)row * C_OUT;
    float m = -1e30f;
    for (int c = lane; c < C_OUT; c += 32) m = fmaxf(m, r[c]);
#pragma unroll
    for (int o = 16; o; o >>= 1) m = fmaxf(m, __shfl_xor_sync(0xffffffffu, m, o));
    float s = 0.f;
    for (int c = lane; c < C_OUT; c += 32) s += expf(r[c] - m);
#pragma unroll
    for (int o = 16; o; o >>= 1) s += __shfl_xor_sync(0xffffffffu, s, o);
    float lse = m + logf(s);
    float* orow = out + (size_t)row * C_OUT;
    for (int c = lane; c < C_OUT; c += 32) orow[c] = r[c] - lse;
}

// ---------------- launch ---------------------------------------------------------
extern "C" void kernel_launch(void* const* d_in, const int* in_sizes, int n_in,
                              void* d_out, int out_size) {
    const float* x     = (const float*)d_in[0];
    const void*  edges = d_in[1];
    const float* W1    = (const float*)d_in[2];
    const float* b1    = (const float*)d_in[3];
    const float* W2    = (const float*)d_in[4];
    const float* b2    = (const float*)d_in[5];
    float* out = (float*)d_out;

    const int E = in_sizes[1] / 2;
    const int N = N_NODES;

    detect_edges_k<<<1, 1>>>(edges);
    conv_edges_k<<<(2 * E + 255) / 256, 256>>>(edges, 2 * E);

    // CSR build + dinv
    init0_k    <<<(N + 255) / 256, 256>>>(N);
    cnt_k      <<<(E + 255) / 256, 256>>>(E);
    scan_dinv_k<<<1, 512>>>();
    scatter_k  <<<(E + 255) / 256, 256>>>(E);

    // bf16 conversions
    conv_x_k  <<<dim3((K_PAD + 255) / 256, N), 256>>>(x);
    conv_w1t_k<<<dim3(K_PAD / 32, HID / 32), dim3(32, 8)>>>(W1);

    // layer 1: GEMM (tensor cores) -> fused CSR aggregate/bias/relu/dropout
    gemm1_tc_k<<<dim3(HID / BN, (N + BM - 1) / BM), 256>>>();
    spmm1_k<<<N, 256>>>(b1);

    // layer 2: proven R5 path
    const int tot2 = N * C_OUT;
    gemm2_k     <<<(tot2 + 255) / 256, 256>>>(W2, tot2);
    agg2_init_k <<<(tot2 + 255) / 256, 256>>>(b2, tot2);
    agg2_edges_k<<<(E + 7) / 8, 256>>>(E);

    logsoftmax_k<<<(N + 7) / 8, 256>>>(out, N);
}

// round 10
// speedup vs baseline: 6.1622x; 1.1847x over previous
#include <cuda_runtime.h>
#include <cuda_bf16.h>
#include <stdint.h>

// Problem dims (fixed)
#define N_NODES 20000
#define F_IN    8710
#define K_PAD   8768          // 274 * 32
#define HID     1024
#define C_OUT   70
#define E_MAX   320000
#define K2CAT   3072          // [hi | hi | lo] x 1024

// GEMM tiling
#define BM 128
#define BN 128
#define BK 32
#define APAD 40               // smem row stride (80B, 16B aligned, conflict-free)

// ---------------- scratch ----------------------------------------------------
__device__ float g_dinv[N_NODES];
__device__ int   g_cnt [N_NODES];
__device__ int   g_cur [N_NODES];
__device__ int   g_rowptr[N_NODES + 1];
__device__ int   g_csrc[E_MAX];
__device__ __nv_bfloat16 g_xb [(size_t)N_NODES * K_PAD];  // x bf16, K-padded
__device__ __nv_bfloat16 g_w1t[(size_t)HID * K_PAD];      // W1^T bf16
__device__ __nv_bfloat16 g_a1c[(size_t)N_NODES * K2CAT];  // a1 split: [hi|hi|lo]
__device__ __nv_bfloat16 g_w2c[(size_t)128 * K2CAT];      // W2^T cat: [Whi;Wlo;Whi]
__device__ float g_h1  [(size_t)N_NODES * HID];
__device__ float g_h2p [(size_t)N_NODES * 128];           // gemm2 out, padded to 128
__device__ float g_o2  [(size_t)N_NODES * C_OUT];
__device__ int   g_edges[2 * E_MAX];
__device__ int   g_is64;

__device__ __forceinline__ uint32_t smem_u32(const void* p) {
    uint32_t a;
    asm("{ .reg .u64 t; cvta.to.shared.u64 t, %1; cvt.u32.u64 %0, t; }" : "=r"(a) : "l"(p));
    return a;
}

// ---------------- edge dtype detection + normalization ----------------------
__global__ void detect_edges_k(const void* edges) {
    const long long* p = (const long long*)edges;
    int valid = 0;
    for (int i = 0; i < 256; i++) {
        long long v = p[i];
        if (v >= 0 && v < N_NODES) valid++;
    }
    g_is64 = (valid >= 200) ? 1 : 0;
}
__global__ void conv_edges_k(const void* edges, int total) {
    int i = blockIdx.x * blockDim.x + threadIdx.x;
    if (i >= total) return;
    long long v = g_is64 ? ((const long long*)edges)[i]
                         : (long long)((const int*)edges)[i];
    g_edges[i] = (int)v;
}

// ---------------- CSR build ---------------------------------------------------
__global__ void init0_k(int n) {
    int i = blockIdx.x * blockDim.x + threadIdx.x;
    if (i < n) { g_cnt[i] = 0; g_cur[i] = 0; }
}
__global__ void cnt_k(int E) {
    int e = blockIdx.x * blockDim.x + threadIdx.x;
    if (e < E) atomicAdd(&g_cnt[g_edges[E + e]], 1);
}
__global__ void scan_dinv_k() {
    __shared__ int part[512];
    const int t = threadIdx.x;
    const int CH = (N_NODES + 511) / 512;   // 40
    const int base = t * CH;
    int sum = 0;
    for (int j = 0; j < CH; j++) {
        int n = base + j;
        if (n < N_NODES) sum += g_cnt[n];
    }
    part[t] = sum;
    __syncthreads();
    for (int off = 1; off < 512; off <<= 1) {
        int v = (t >= off) ? part[t - off] : 0;
        __syncthreads();
        part[t] += v;
        __syncthreads();
    }
    int run = (t > 0) ? part[t - 1] : 0;
    for (int j = 0; j < CH; j++) {
        int n = base + j;
        if (n < N_NODES) {
            g_rowptr[n] = run;
            int c = g_cnt[n];
            run += c;
            g_dinv[n] = rsqrtf((float)(c + 1));
        }
    }
    if (t == 511) g_rowptr[N_NODES] = run;
}
__global__ void scatter_k(int E) {
    int e = blockIdx.x * blockDim.x + threadIdx.x;
    if (e >= E) return;
    int s = g_edges[e];
    int d = g_edges[E + e];
    int pos = g_rowptr[d] + atomicAdd(&g_cur[d], 1);
    g_csrc[pos] = s;
}

// ---------------- conversions -------------------------------------------------
__global__ void conv_x_k(const float* __restrict__ x) {
    int k = blockIdx.x * 256 + threadIdx.x;
    int r = blockIdx.y;
    if (k >= K_PAD) return;
    float v = (k < F_IN) ? x[(size_t)r * F_IN + k] : 0.f;
    g_xb[(size_t)r * K_PAD + k] = __float2bfloat16(v);
}
__global__ void conv_w1t_k(const float* __restrict__ W1) {
    __shared__ __nv_bfloat16 t[32][33];
    int k0 = blockIdx.x * 32, n0 = blockIdx.y * 32;
    int tx = threadIdx.x, ty = threadIdx.y;
#pragma unroll
    for (int i = 0; i < 32; i += 8) {
        int k = k0 + ty + i, n = n0 + tx;
        float v = (k < F_IN) ? W1[(size_t)k * HID + n] : 0.f;
        t[ty + i][tx] = __float2bfloat16(v);
    }
    __syncthreads();
#pragma unroll
    for (int i = 0; i < 32; i += 8) {
        int n = n0 + ty + i, k = k0 + tx;
        g_w1t[(size_t)n * K_PAD + k] = t[tx][ty + i];
    }
}
// W2 cat: rows n (0..127), cols kk (0..3071): seg0=Whi, seg1=Wlo, seg2=Whi
__global__ void conv_w2c_k(const float* __restrict__ W2) {
    int idx = blockIdx.x * 256 + threadIdx.x;
    if (idx >= 128 * K2CAT) return;
    int n = idx / K2CAT, kk = idx - n * K2CAT;
    int seg = kk >> 10, k = kk & 1023;
    float w = (n < C_OUT) ? W2[(size_t)k * C_OUT + n] : 0.f;
    __nv_bfloat16 hi = __float2bfloat16(w);
    __nv_bfloat16 v;
    if (seg == 1) v = __float2bfloat16(w - __bfloat162float(hi));  // Wlo
    else          v = hi;                                          // Whi
    g_w2c[(size_t)n * K2CAT + kk] = v;
}

// ---------------- bf16 HMMA GEMM body (device-side pointer binding!) ----------
// NOTE: __device__ globals must NEVER be passed as kernel args from host code —
// on GB300 (ATS) the host-shadow address is silently readable/writable and the
// kernel runs on zeros (R6/R8 failure). Pointers are bound in device code here.
__device__ __forceinline__ void ldsm_x4(uint32_t* r, uint32_t addr) {
    asm volatile("ldmatrix.sync.aligned.m8n8.x4.shared.b16 {%0,%1,%2,%3}, [%4];"
        : "=r"(r[0]), "=r"(r[1]), "=r"(r[2]), "=r"(r[3]) : "r"(addr));
}
__device__ __forceinline__ void ldsm_x2(uint32_t* r, uint32_t addr) {
    asm volatile("ldmatrix.sync.aligned.m8n8.x2.shared.b16 {%0,%1}, [%2];"
        : "=r"(r[0]), "=r"(r[1]) : "r"(addr));
}
__device__ __forceinline__ void mma16816(float* d, const uint32_t* a, const uint32_t* b) {
    asm volatile(
        "mma.sync.aligned.m16n8k16.row.col.f32.bf16.bf16.f32 "
        "{%0,%1,%2,%3}, {%4,%5,%6,%7}, {%8,%9}, {%0,%1,%2,%3};"
        : "+f"(d[0]), "+f"(d[1]), "+f"(d[2]), "+f"(d[3])
        : "r"(a[0]), "r"(a[1]), "r"(a[2]), "r"(a[3]), "r"(b[0]), "r"(b[1]));
}
#define CP_ASYNC16(dst, src) \
    asm volatile("cp.async.cg.shared.global [%0], [%1], 16;" :: "r"(dst), "l"(src))
#define CP_COMMIT() asm volatile("cp.async.commit_group;" ::: "memory")
#define CP_WAIT0()  asm volatile("cp.async.wait_group 0;" ::: "memory")

template<int KT>
__device__ __forceinline__ void gemm_body(
    const __nv_bfloat16* Asrc, const __nv_bfloat16* Bsrc,
    int kstride, float* dst, int dstride)
{
    __shared__ __align__(16) __nv_bfloat16 As[2][BM * APAD];
    __shared__ __align__(16) __nv_bfloat16 Bs[2][BN * APAD];

    const int tid  = threadIdx.x;
    const int wid  = tid >> 5, lane = tid & 31;
    const int mBase = blockIdx.y * BM;
    const int nBase = blockIdx.x * BN;
    const int mo = (wid >> 2) * 64;
    const int no = (wid & 3) * 32;

    const int r0 = tid >> 2, c0 = (tid & 3) * 8;
    const int r1 = (tid + 256) >> 2, c1 = c0;
    const int amr0 = (mBase + r0 < N_NODES) ? mBase + r0 : N_NODES - 1;
    const int amr1 = (mBase + r1 < N_NODES) ? mBase + r1 : N_NODES - 1;
    const __nv_bfloat16* aSrc0 = Asrc + (size_t)amr0 * kstride + c0;
    const __nv_bfloat16* aSrc1 = Asrc + (size_t)amr1 * kstride + c1;
    const __nv_bfloat16* bSrc0 = Bsrc + (size_t)(nBase + r0) * kstride + c0;
    const __nv_bfloat16* bSrc1 = Bsrc + (size_t)(nBase + r1) * kstride + c1;

    uint32_t aDst0[2], aDst1[2], bDst0[2], bDst1[2];
#pragma unroll
    for (int s = 0; s < 2; s++) {
        aDst0[s] = smem_u32(&As[s][r0 * APAD + c0]);
        aDst1[s] = smem_u32(&As[s][r1 * APAD + c1]);
        bDst0[s] = smem_u32(&Bs[s][r0 * APAD + c0]);
        bDst1[s] = smem_u32(&Bs[s][r1 * APAD + c1]);
    }

    const int lg = lane >> 3, lr = lane & 7;
    const uint32_t aLdBase[2] = {
        smem_u32(&As[0][(mo + (lg & 1) * 8 + lr) * APAD + (lg >> 1) * 8]),
        smem_u32(&As[1][(mo + (lg & 1) * 8 + lr) * APAD + (lg >> 1) * 8]) };
    const int bl = lane & 15, bg = bl >> 3, br = bl & 7;
    const uint32_t bLdBase[2] = {
        smem_u32(&Bs[0][(no + br) * APAD + bg * 8]),
        smem_u32(&Bs[1][(no + br) * APAD + bg * 8]) };

    float acc[4][4][4];
#pragma unroll
    for (int i = 0; i < 4; i++)
#pragma unroll
        for (int j = 0; j < 4; j++)
#pragma unroll
            for (int q = 0; q < 4; q++) acc[i][j][q] = 0.f;

    CP_ASYNC16(aDst0[0], aSrc0);
    CP_ASYNC16(aDst1[0], aSrc1);
    CP_ASYNC16(bDst0[0], bSrc0);
    CP_ASYNC16(bDst1[0], bSrc1);
    CP_COMMIT();

    for (int it = 0; it < KT; it++) {
        const int s = it & 1;
        CP_WAIT0();
        __syncthreads();
        if (it + 1 < KT) {
            const int ns = s ^ 1;
            const size_t ko = (size_t)(it + 1) * BK;
            CP_ASYNC16(aDst0[ns], aSrc0 + ko);
            CP_ASYNC16(aDst1[ns], aSrc1 + ko);
            CP_ASYNC16(bDst0[ns], bSrc0 + ko);
            CP_ASYNC16(bDst1[ns], bSrc1 + ko);
            CP_COMMIT();
        }
#pragma unroll
        for (int ks = 0; ks < 2; ks++) {
            uint32_t a[4][4], b[4][2];
#pragma unroll
            for (int mi = 0; mi < 4; mi++)
                ldsm_x4(a[mi], aLdBase[s] + (mi * 16 * APAD + ks * 16) * 2);
#pragma unroll
            for (int nj = 0; nj < 4; nj++)
                ldsm_x2(b[nj], bLdBase[s] + (nj * 8 * APAD + ks * 16) * 2);
#pragma unroll
            for (int mi = 0; mi < 4; mi++)
#pragma unroll
                for (int nj = 0; nj < 4; nj++)
                    mma16816(acc[mi][nj], a[mi], b[nj]);
        }
        __syncthreads();
    }

    const int erow = lane >> 2, ecol = (lane & 3) * 2;
#pragma unroll
    for (int mi = 0; mi < 4; mi++) {
        const int gr0 = mBase + mo + mi * 16 + erow;
        const int gr1 = gr0 + 8;
#pragma unroll
        for (int nj = 0; nj < 4; nj++) {
            const int gc = nBase + no + nj * 8 + ecol;
            if (gr0 < N_NODES)
                *(float2*)(dst + (size_t)gr0 * dstride + gc) = make_float2(acc[mi][nj][0], acc[mi][nj][1]);
            if (gr1 < N_NODES)
                *(float2*)(dst + (size_t)gr1 * dstride + gc) = make_float2(acc[mi][nj][2], acc[mi][nj][3]);
        }
    }
}

// Thin wrappers: pointers bound IN DEVICE CODE (real device addresses).
__global__ __launch_bounds__(256) void gemm1_k() {
    gemm_body<K_PAD / BK>(g_xb, g_w1t, K_PAD, g_h1, HID);
}
__global__ __launch_bounds__(256) void gemm2_k() {
    gemm_body<K2CAT / BK>(g_a1c, g_w2c, K2CAT, g_h2p, 128);
}

// ---------------- threefry (JAX partitionable, key=(0,42)) --------------------
__device__ __forceinline__ uint32_t tf_bits(uint32_t i) {
    const uint32_t ks0 = 0u, ks1 = 42u, ks2 = 0u ^ 42u ^ 0x1BD11BDAu;
    uint32_t x0 = 0u + ks0;
    uint32_t x1 = i + ks1;
#define TF_RND(r) { x0 += x1; x1 = (x1 << (r)) | (x1 >> (32 - (r))); x1 ^= x0; }
    TF_RND(13) TF_RND(15) TF_RND(26) TF_RND(6)   x0 += ks1; x1 += ks2 + 1u;
    TF_RND(17) TF_RND(29) TF_RND(16) TF_RND(24)  x0 += ks2; x1 += ks0 + 2u;
    TF_RND(13) TF_RND(15) TF_RND(26) TF_RND(6)   x0 += ks0; x1 += ks1 + 3u;
    TF_RND(17) TF_RND(29) TF_RND(16) TF_RND(24)  x0 += ks1; x1 += ks2 + 4u;
    TF_RND(13) TF_RND(15) TF_RND(26) TF_RND(6)   x0 += ks2; x1 += ks0 + 5u;
#undef TF_RND
    return x0 ^ x1;
}

// ---------------- fused agg1 + bias + relu + dropout -> split bf16 ------------
__global__ __launch_bounds__(256) void spmm1_k(const float* __restrict__ b1) {
    __shared__ int sidx[512];
    const int d = blockIdx.x;
    const int tid = threadIdx.x;
    const float di = g_dinv[d];
    const int beg = g_rowptr[d], end = g_rowptr[d + 1];

    float4 acc = *(const float4*)(g_h1 + (size_t)d * HID + tid * 4);
    const float dii = di * di;
    acc.x *= dii; acc.y *= dii; acc.z *= dii; acc.w *= dii;
    float4 bv = *(const float4*)(b1 + tid * 4);
    acc.x += bv.x; acc.y += bv.y; acc.z += bv.z; acc.w += bv.w;

    for (int chunk = beg; chunk < end; chunk += 512) {
        int n = min(512, end - chunk);
        __syncthreads();
        if (tid < n)       sidx[tid]       = g_csrc[chunk + tid];
        if (tid + 256 < n) sidx[tid + 256] = g_csrc[chunk + tid + 256];
        __syncthreads();
        for (int i = 0; i < n; i++) {
            int s = sidx[i];
            float w = g_dinv[s] * di;
            float4 v = *(const float4*)(g_h1 + (size_t)s * HID + tid * 4);
            acc.x += v.x * w; acc.y += v.y * w; acc.z += v.z * w; acc.w += v.w * w;
        }
    }

    const uint32_t idx = (uint32_t)d * HID + tid * 4;
    float v[4];
    v[0] = fmaxf(acc.x, 0.f); v[1] = fmaxf(acc.y, 0.f);
    v[2] = fmaxf(acc.z, 0.f); v[3] = fmaxf(acc.w, 0.f);
#pragma unroll
    for (int q = 0; q < 4; q++)
        v[q] = (tf_bits(idx + q) & 0x80000000u) ? 0.f : 2.f * v[q];

    __nv_bfloat16 hi[4], lo[4];
#pragma unroll
    for (int q = 0; q < 4; q++) {
        hi[q] = __float2bfloat16(v[q]);
        lo[q] = __float2bfloat16(v[q] - __bfloat162float(hi[q]));
    }
    uint2 phi, plo;
    {
        __nv_bfloat162 h0 = __nv_bfloat162(hi[0], hi[1]);
        __nv_bfloat162 h1 = __nv_bfloat162(hi[2], hi[3]);
        __nv_bfloat162 l0 = __nv_bfloat162(lo[0], lo[1]);
        __nv_bfloat162 l1 = __nv_bfloat162(lo[2], lo[3]);
        phi.x = *(uint32_t*)&h0; phi.y = *(uint32_t*)&h1;
        plo.x = *(uint32_t*)&l0; plo.y = *(uint32_t*)&l1;
    }
    __nv_bfloat16* row = g_a1c + (size_t)d * K2CAT + tid * 4;
    *(uint2*)(row)        = phi;   // seg 0: hi
    *(uint2*)(row + 1024) = phi;   // seg 1: hi
    *(uint2*)(row + 2048) = plo;   // seg 2: lo
}

// ---------------- agg2 (atomic path, reading padded h2) -----------------------
__global__ void agg2_init_k(const float* __restrict__ b2, int total) {
    int idx = blockIdx.x * blockDim.x + threadIdx.x;
    if (idx >= total) return;
    int n = idx / C_OUT, c = idx - n * C_OUT;
    float di = g_dinv[n];
    g_o2[idx] = b2[c] + g_h2p[(size_t)n * 128 + c] * di * di;
}
__global__ void agg2_edges_k(int E) {
    int warp = (blockIdx.x * blockDim.x + threadIdx.x) >> 5;
    int lane = threadIdx.x & 31;
    if (warp >= E) return;
    int s = g_edges[warp];
    int d = g_edges[E + warp];
    float w = g_dinv[s] * g_dinv[d];
    const float* hs = g_h2p + (size_t)s * 128;
    float* od = g_o2 + (size_t)d * C_OUT;
    for (int c = lane; c < C_OUT; c += 32)
        atomicAdd(od + c, hs[c] * w);
}

// ---------------- log_softmax ---------------------------------------------------
__global__ void logsoftmax_k(float* __restrict__ out, int n) {
    int row  = blockIdx.x * 8 + (threadIdx.x >> 5);
    int lane = threadIdx.x & 31;
    if (row >= n) return;
    const float* r = g_o2 + (size_t)row * C_OUT;
    float m = -1e30f;
    for (int c = lane; c < C_OUT; c += 32) m = fmaxf(m, r[c]);
#pragma unroll
    for (int o = 16; o; o >>= 1) m = fmaxf(m, __shfl_xor_sync(0xffffffffu, m, o));
    float s = 0.f;
    for (int c = lane; c < C_OUT; c += 32) s += expf(r[c] - m);
#pragma unroll
    for (int o = 16; o; o >>= 1) s += __shfl_xor_sync(0xffffffffu, s, o);
    float lse = m + logf(s);
    float* orow = out + (size_t)row * C_OUT;
    for (int c = lane; c < C_OUT; c += 32) orow[c] = r[c] - lse;
}

// ---------------- launch ---------------------------------------------------------
extern "C" void kernel_launch(void* const* d_in, const int* in_sizes, int n_in,
                              void* d_out, int out_size) {
    const float* x     = (const float*)d_in[0];
    const void*  edges = d_in[1];
    const float* W1    = (const float*)d_in[2];
    const float* b1    = (const float*)d_in[3];
    const float* W2    = (const float*)d_in[4];
    const float* b2    = (const float*)d_in[5];
    float* out = (float*)d_out;

    const int E = in_sizes[1] / 2;
    const int N = N_NODES;

    detect_edges_k<<<1, 1>>>(edges);
    conv_edges_k<<<(2 * E + 255) / 256, 256>>>(edges, 2 * E);

    // CSR build + dinv
    init0_k    <<<(N + 255) / 256, 256>>>(N);
    cnt_k      <<<(E + 255) / 256, 256>>>(E);
    scan_dinv_k<<<1, 512>>>();
    scatter_k  <<<(E + 255) / 256, 256>>>(E);

    // bf16 conversions
    conv_x_k  <<<dim3((K_PAD + 255) / 256, N), 256>>>(x);
    conv_w1t_k<<<dim3(K_PAD / 32, HID / 32), dim3(32, 8)>>>(W1);
    conv_w2c_k<<<(128 * K2CAT + 255) / 256, 256>>>(W2);

    // layer 1: HMMA GEMM -> fused CSR aggregate/bias/relu/dropout -> split bf16
    gemm1_k<<<dim3(HID / BN, (N + BM - 1) / BM), 256>>>();
    spmm1_k<<<N, 256>>>(b1);

    // layer 2: HMMA GEMM on split operands (hi*Whi + hi*Wlo + lo*Whi)
    gemm2_k<<<dim3(1, (N + BM - 1) / BM), 256>>>();

    // agg2 + log_softmax
    const int tot2 = N * C_OUT;
    agg2_init_k <<<(tot2 + 255) / 256, 256>>>(b2, tot2);
    agg2_edges_k<<<(E + 7) / 8, 256>>>(E);
    logsoftmax_k<<<(N + 7) / 8, 256>>>(out, N);
}